// round 1
// baseline (speedup 1.0000x reference)
#include <cuda_runtime.h>
#include <cuda_bf16.h>

// GrahamLoss: loss = sum_b sum_{c,d} ( (D Dᵀ)_{b,c,d} - (F Fᵀ)_{b,c,d} )² / (4·HW²·C²)
// F,D: [B=16, C=512, H=32, W=32] fp32, HW=1024 contiguous per row.
//
// Strategy: fused per-tile dual-Gram. Each CTA owns one 64x64 tile (I,J), I<=J,
// of one batch's Gram, accumulates enc & dec tiles over K=1024 in chunks of 16,
// squares the difference locally, block-reduces, writes a weighted partial
// (x2 for off-diagonal tiles by symmetry). A second kernel reduces 576 partials
// deterministically and applies 1/denom.

#define B_   16
#define C_   512
#define HW_  1024
#define BT   64      // tile (rows of I-block and J-block)
#define KC   16      // K chunk
#define NTILES 36    // 8x8 upper triangle incl diag
#define NPART (NTILES * B_)

__device__ float g_partials[NPART];

__global__ __launch_bounds__(256, 2)
void gram_tile_kernel(const float* __restrict__ F, const float* __restrict__ D) {
    const int b   = blockIdx.y;
    const int tid = threadIdx.x;

    // map blockIdx.x -> (I, J) with I <= J over 8x8 tile grid
    int rem = blockIdx.x;
    int I = 0;
    #pragma unroll
    for (int r = 8; r >= 1; r--) {
        if (rem < r) break;
        rem -= r; I++;
    }
    const int J = I + rem;
    const float w = (I == J) ? 1.0f : 2.0f;

    const float* Fb = F + (size_t)b * C_ * HW_;
    const float* Db = D + (size_t)b * C_ * HW_;

    // K-transposed smem tiles: s[k][row]
    __shared__ float sFI[KC][BT];
    __shared__ float sFJ[KC][BT];
    __shared__ float sDI[KC][BT];
    __shared__ float sDJ[KC][BT];

    // loader mapping: each thread loads one float4 per tile per chunk
    const int lr = tid & 63;        // row within tile
    const int kq = tid >> 6;        // which float4 along k (0..3)

    const float* pFI = Fb + (size_t)(I * BT + lr) * HW_ + 4 * kq;
    const float* pFJ = Fb + (size_t)(J * BT + lr) * HW_ + 4 * kq;
    const float* pDI = Db + (size_t)(I * BT + lr) * HW_ + 4 * kq;
    const float* pDJ = Db + (size_t)(J * BT + lr) * HW_ + 4 * kq;

    // compute mapping: 16x16 threads, 4x4 outputs each
    const int tx = tid & 15;
    const int ty = tid >> 4;

    float accE[4][4], accD[4][4];
    #pragma unroll
    for (int i = 0; i < 4; i++)
        #pragma unroll
        for (int j = 0; j < 4; j++) { accE[i][j] = 0.f; accD[i][j] = 0.f; }

    // prefetch chunk 0
    float4 rFI = *(const float4*)(pFI);
    float4 rFJ = *(const float4*)(pFJ);
    float4 rDI = *(const float4*)(pDI);
    float4 rDJ = *(const float4*)(pDJ);

    const int nChunks = HW_ / KC;   // 64
    for (int c = 0; c < nChunks; c++) {
        __syncthreads();   // previous compute done before overwriting smem
        {
            const float* vFI = (const float*)&rFI;
            const float* vFJ = (const float*)&rFJ;
            const float* vDI = (const float*)&rDI;
            const float* vDJ = (const float*)&rDJ;
            #pragma unroll
            for (int j = 0; j < 4; j++) {
                sFI[4 * kq + j][lr] = vFI[j];
                sFJ[4 * kq + j][lr] = vFJ[j];
                sDI[4 * kq + j][lr] = vDI[j];
                sDJ[4 * kq + j][lr] = vDJ[j];
            }
        }
        __syncthreads();

        // prefetch next chunk while computing this one
        if (c + 1 < nChunks) {
            const int off = (c + 1) * KC;
            rFI = *(const float4*)(pFI + off);
            rFJ = *(const float4*)(pFJ + off);
            rDI = *(const float4*)(pDI + off);
            rDJ = *(const float4*)(pDJ + off);
        }

        #pragma unroll
        for (int k = 0; k < KC; k++) {
            float4 aE = *(const float4*)&sFI[k][ty * 4];
            float4 bE = *(const float4*)&sFJ[k][tx * 4];
            float4 aD = *(const float4*)&sDI[k][ty * 4];
            float4 bD = *(const float4*)&sDJ[k][tx * 4];
            const float* ae = (const float*)&aE;
            const float* be = (const float*)&bE;
            const float* ad = (const float*)&aD;
            const float* bd = (const float*)&bD;
            #pragma unroll
            for (int i = 0; i < 4; i++) {
                #pragma unroll
                for (int j = 0; j < 4; j++) {
                    accE[i][j] = fmaf(ae[i], be[j], accE[i][j]);
                    accD[i][j] = fmaf(ad[i], bd[j], accD[i][j]);
                }
            }
        }
    }

    // local diff^2 sum
    float local = 0.f;
    #pragma unroll
    for (int i = 0; i < 4; i++)
        #pragma unroll
        for (int j = 0; j < 4; j++) {
            float dv = accD[i][j] - accE[i][j];
            local = fmaf(dv, dv, local);
        }

    // block reduction (deterministic)
    __shared__ float red[256];
    __syncthreads();            // smem tiles no longer needed
    red[tid] = local;
    __syncthreads();
    #pragma unroll
    for (int st = 128; st > 0; st >>= 1) {
        if (tid < st) red[tid] += red[tid + st];
        __syncthreads();
    }
    if (tid == 0)
        g_partials[b * NTILES + blockIdx.x] = w * red[0];
}

__global__ void reduce_kernel(float* __restrict__ out) {
    __shared__ float s[256];
    const int tid = threadIdx.x;
    float v = 0.f;
    for (int i = tid; i < NPART; i += 256) v += g_partials[i];
    s[tid] = v;
    __syncthreads();
    #pragma unroll
    for (int st = 128; st > 0; st >>= 1) {
        if (tid < st) s[tid] += s[tid + st];
        __syncthreads();
    }
    if (tid == 0) {
        // denom = 4 * HW^2 * C^2 = 2^40
        const float inv_denom = 1.0f / 1099511627776.0f;
        out[0] = s[0] * inv_denom;
    }
}

extern "C" void kernel_launch(void* const* d_in, const int* in_sizes, int n_in,
                              void* d_out, int out_size) {
    const float* F = (const float*)d_in[0];   // feat
    const float* D = (const float*)d_in[1];   // feat_decod
    float* out = (float*)d_out;

    dim3 grid(NTILES, B_);
    gram_tile_kernel<<<grid, 256>>>(F, D);
    reduce_kernel<<<1, 256>>>(out);
}

// round 4
// speedup vs baseline: 4.8597x; 4.8597x over previous
#include <cuda_runtime.h>
#include <cuda_bf16.h>
#include <cstdint>

// GrahamLoss via legacy mma.sync (bf16, sm_100-compatible PTX).
// loss = sum_b ||D_b D_b^T - F_b F_b^T||_F^2 / 2^40,  F,D: [16,512,32,32] fp32.
// One CTA per 128x128 Gram tile over the upper triangle (x2 off-diagonal).

#define B_    16
#define C_    512
#define HW_   1024
#define TM    128
#define KC    32            // k per chunk (fp32 elems)
#define NCH   (HW_ / KC)    // 32
#define NT    10
#define NPART (B_ * NT)     // 160
#define PANEL_B 8192        // 128 rows * 64 B (32 bf16)
#define STAGE_B (4 * PANEL_B)
#define DYN_SMEM (2 * STAGE_B)   // 64 KB

__device__ float        g_partials[NPART];
__device__ unsigned int g_count;

__constant__ int c_tileI[NT] = {0,0,0,0,1,1,1,2,2,3};
__constant__ int c_tileJ[NT] = {0,1,2,3,1,2,3,2,3,3};

// ---------- helpers ----------
__device__ __forceinline__ uint32_t smem_u32(const void* p) {
    uint32_t a;
    asm("{ .reg .u64 t; cvta.to.shared.u64 t, %1; cvt.u32.u64 %0, t; }" : "=r"(a) : "l"(p));
    return a;
}
// swizzled byte offset within a panel: row in [0,128), k = bf16 column in [0,32)
__device__ __forceinline__ uint32_t swz(uint32_t row, uint32_t k) {
    return row * 64u + ((((k >> 3) ^ (row >> 1)) & 3u) << 4) + (k & 7u) * 2u;
}
__device__ __forceinline__ uint32_t pack2(float hi, float lo) {
    uint32_t r;
    asm("cvt.rn.bf16x2.f32 %0, %1, %2;" : "=r"(r) : "f"(hi), "f"(lo));
    return r;
}
__device__ __forceinline__ void sts64(uint32_t addr, uint32_t a, uint32_t b) {
    asm volatile("st.shared.v2.b32 [%0], {%1, %2};" :: "r"(addr), "r"(a), "r"(b) : "memory");
}
__device__ __forceinline__ void ldm_x4(uint32_t* r, uint32_t addr) {
    asm volatile("ldmatrix.sync.aligned.m8n8.x4.shared.b16 {%0,%1,%2,%3}, [%4];"
                 : "=r"(r[0]), "=r"(r[1]), "=r"(r[2]), "=r"(r[3]) : "r"(addr));
}
__device__ __forceinline__ void mma_bf16(float* d, const uint32_t* a, const uint32_t* b) {
    asm volatile("mma.sync.aligned.m16n8k16.row.col.f32.bf16.bf16.f32 "
                 "{%0,%1,%2,%3}, {%4,%5,%6,%7}, {%8,%9}, {%0,%1,%2,%3};"
                 : "+f"(d[0]), "+f"(d[1]), "+f"(d[2]), "+f"(d[3])
                 : "r"(a[0]), "r"(a[1]), "r"(a[2]), "r"(a[3]), "r"(b[0]), "r"(b[1]));
}

// ---------- main kernel ----------
__global__ __launch_bounds__(256, 1)
void gram_kernel(const float* __restrict__ F, const float* __restrict__ Dm,
                 float* __restrict__ out) {
    extern __shared__ __align__(128) unsigned char smem[];
    __shared__ float red[256];
    __shared__ unsigned int s_islast;

    const int tid  = threadIdx.x;
    const int lane = tid & 31;
    const int wid  = tid >> 5;
    const int b    = blockIdx.y;
    const int I = c_tileI[blockIdx.x];
    const int J = c_tileJ[blockIdx.x];
    const int diag = (I == J);
    const float w = diag ? 1.0f : 2.0f;

    const float* gp[4];
    gp[0] = F  + ((size_t)b * C_ + I * TM) * HW_;   // FI (A of enc)
    gp[1] = F  + ((size_t)b * C_ + J * TM) * HW_;   // FJ (B of enc)
    gp[2] = Dm + ((size_t)b * C_ + I * TM) * HW_;   // DI (A of dec)
    gp[3] = Dm + ((size_t)b * C_ + J * TM) * HW_;   // DJ (B of dec)

    const uint32_t sbase = smem_u32(smem);

    // loader coords: idx = i*256+tid -> row = idx>>3 (0..127), seg = idx&7 (8 float4 per row)
    const int lrow0 = tid >> 3;        // i contributes +32 rows per step
    const int lseg  = tid & 7;

    // warp tiling: 2x4 warps, warp tile 64(m) x 32(n)
    const int wm = wid >> 2;
    const int wn = wid & 3;
    // ldmatrix lane addressing
    const int a_row = (lane & 15);            // + m_base + mt*16
    const int a_k   = (lane >> 4) << 3;       // + k0
    const int b_row = (((lane >> 4) & 1) << 3) + (lane & 7);  // + n_base + tp*16
    const int b_k   = ((lane >> 3) & 1) << 3; // + k0

    float accE[4][4][4];
    float accD[4][4][4];
    #pragma unroll
    for (int mt = 0; mt < 4; mt++)
        #pragma unroll
        for (int nt = 0; nt < 4; nt++)
            #pragma unroll
            for (int r = 0; r < 4; r++) { accE[mt][nt][r] = 0.f; accD[mt][nt][r] = 0.f; }

    // ---- prologue: load chunk 0 into stage 0 ----
    #pragma unroll
    for (int p = 0; p < 4; p++) {
        if (diag && (p & 1)) continue;
        #pragma unroll
        for (int i = 0; i < 4; i++) {
            int row = lrow0 + i * 32;
            float4 v = *(const float4*)(gp[p] + (size_t)row * HW_ + lseg * 4);
            sts64(sbase + p * PANEL_B + swz(row, lseg * 4), pack2(v.y, v.x), pack2(v.w, v.z));
        }
    }
    __syncthreads();

    // ---- main loop ----
    for (int c = 0; c < NCH; c++) {
        const int s = c & 1;
        const uint32_t stb = sbase + s * STAGE_B;
        const uint32_t pAE = stb + 0 * PANEL_B;
        const uint32_t pBE = stb + (diag ? 0 : 1) * PANEL_B;
        const uint32_t pAD = stb + 2 * PANEL_B;
        const uint32_t pBD = stb + (diag ? 2 : 3) * PANEL_B;
        const bool more = (c + 1 < NCH);
        const int k1 = (c + 1) * KC;
        const uint32_t nstb = sbase + (s ^ 1) * STAGE_B;

        // batch 1 loads (panels 0,1) overlap enc MMA
        float4 st[8];
        if (more) {
            #pragma unroll
            for (int p = 0; p < 2; p++) {
                if (diag && p == 1) continue;
                #pragma unroll
                for (int i = 0; i < 4; i++) {
                    int row = lrow0 + i * 32;
                    st[p * 4 + i] = *(const float4*)(gp[p] + (size_t)row * HW_ + k1 + lseg * 4);
                }
            }
        }
        // enc gram MMAs
        #pragma unroll
        for (int ks = 0; ks < 2; ks++) {
            const int k0 = ks * 16;
            uint32_t af[4][4], bf[4][2];
            #pragma unroll
            for (int mt = 0; mt < 4; mt++)
                ldm_x4(af[mt], pAE + swz(wm * 64 + mt * 16 + a_row, k0 + a_k));
            #pragma unroll
            for (int tp = 0; tp < 2; tp++) {
                uint32_t t4[4];
                ldm_x4(t4, pBE + swz(wn * 32 + tp * 16 + b_row, k0 + b_k));
                bf[2 * tp][0] = t4[0]; bf[2 * tp][1] = t4[1];
                bf[2 * tp + 1][0] = t4[2]; bf[2 * tp + 1][1] = t4[3];
            }
            #pragma unroll
            for (int mt = 0; mt < 4; mt++)
                #pragma unroll
                for (int nt = 0; nt < 4; nt++)
                    mma_bf16(accE[mt][nt], af[mt], bf[nt]);
        }
        // store batch 1, issue batch 2 loads (panels 2,3) overlapping dec MMA
        if (more) {
            #pragma unroll
            for (int p = 0; p < 2; p++) {
                if (diag && p == 1) continue;
                #pragma unroll
                for (int i = 0; i < 4; i++) {
                    int row = lrow0 + i * 32;
                    float4 v = st[p * 4 + i];
                    sts64(nstb + p * PANEL_B + swz(row, lseg * 4),
                          pack2(v.y, v.x), pack2(v.w, v.z));
                }
            }
            #pragma unroll
            for (int p = 2; p < 4; p++) {
                if (diag && p == 3) continue;
                #pragma unroll
                for (int i = 0; i < 4; i++) {
                    int row = lrow0 + i * 32;
                    st[(p - 2) * 4 + i] = *(const float4*)(gp[p] + (size_t)row * HW_ + k1 + lseg * 4);
                }
            }
        }
        // dec gram MMAs
        #pragma unroll
        for (int ks = 0; ks < 2; ks++) {
            const int k0 = ks * 16;
            uint32_t af[4][4], bf[4][2];
            #pragma unroll
            for (int mt = 0; mt < 4; mt++)
                ldm_x4(af[mt], pAD + swz(wm * 64 + mt * 16 + a_row, k0 + a_k));
            #pragma unroll
            for (int tp = 0; tp < 2; tp++) {
                uint32_t t4[4];
                ldm_x4(t4, pBD + swz(wn * 32 + tp * 16 + b_row, k0 + b_k));
                bf[2 * tp][0] = t4[0]; bf[2 * tp][1] = t4[1];
                bf[2 * tp + 1][0] = t4[2]; bf[2 * tp + 1][1] = t4[3];
            }
            #pragma unroll
            for (int mt = 0; mt < 4; mt++)
                #pragma unroll
                for (int nt = 0; nt < 4; nt++)
                    mma_bf16(accD[mt][nt], af[mt], bf[nt]);
        }
        // store batch 2
        if (more) {
            #pragma unroll
            for (int p = 2; p < 4; p++) {
                if (diag && p == 3) continue;
                #pragma unroll
                for (int i = 0; i < 4; i++) {
                    int row = lrow0 + i * 32;
                    float4 v = st[(p - 2) * 4 + i];
                    sts64(nstb + p * PANEL_B + swz(row, lseg * 4),
                          pack2(v.y, v.x), pack2(v.w, v.z));
                }
            }
        }
        __syncthreads();
    }

    // ---- epilogue: diff^2 over accumulator registers ----
    float local = 0.f;
    #pragma unroll
    for (int mt = 0; mt < 4; mt++)
        #pragma unroll
        for (int nt = 0; nt < 4; nt++)
            #pragma unroll
            for (int r = 0; r < 4; r++) {
                float dv = accD[mt][nt][r] - accE[mt][nt][r];
                local = fmaf(dv, dv, local);
            }

    red[tid] = local;
    __syncthreads();
    #pragma unroll
    for (int stp = 128; stp > 0; stp >>= 1) {
        if (tid < stp) red[tid] += red[tid + stp];
        __syncthreads();
    }

    if (tid == 0) {
        g_partials[b * NT + blockIdx.x] = w * red[0];
        __threadfence();
        unsigned int prev = atomicAdd(&g_count, 1u);
        s_islast = (prev == NPART - 1) ? 1u : 0u;
    }
    __syncthreads();
    if (s_islast) {
        __threadfence();
        float v = 0.f;
        for (int i = tid; i < NPART; i += 256) v += g_partials[i];
        red[tid] = v;
        __syncthreads();
        #pragma unroll
        for (int stp = 128; stp > 0; stp >>= 1) {
            if (tid < stp) red[tid] += red[tid + stp];
            __syncthreads();
        }
        if (tid == 0) {
            out[0] = red[0] * (1.0f / 1099511627776.0f);  // / 2^40
            g_count = 0;  // reset for next graph replay
        }
    }
}

extern "C" void kernel_launch(void* const* d_in, const int* in_sizes, int n_in,
                              void* d_out, int out_size) {
    const float* F = (const float*)d_in[0];   // feat
    const float* D = (const float*)d_in[1];   // feat_decod
    float* out = (float*)d_out;

    cudaFuncSetAttribute(gram_kernel, cudaFuncAttributeMaxDynamicSharedMemorySize, DYN_SMEM);
    dim3 grid(NT, B_);
    gram_kernel<<<grid, 256, DYN_SMEM>>>(F, D, out);
}

// round 5
// speedup vs baseline: 4.9532x; 1.0192x over previous
#include <cuda_runtime.h>
#include <cuda_bf16.h>
#include <cstdint>

// GrahamLoss via legacy mma.sync (bf16). 64x128 half-tiles, 320 CTAs,
// 2 CTAs/SM target. loss = sum_b ||D G - F G||_F^2 / 2^40.

#define B_    16
#define C_    512
#define HW_   1024
#define KC    32            // k per chunk (fp32 elems)
#define NCH   (HW_ / KC)    // 32
#define NPT   10            // parent tiles (4x4 upper triangle)
#define NHT   (2 * NPT)     // 20 half-tiles
#define NPART (B_ * NHT)    // 320

// per-stage smem layout (bytes): BF=0, BD=8K, AF=16K, AD=20K
#define OBF 0
#define OBD 8192
#define OAF 16384
#define OAD 20480
#define STG 24576
#define DYN_SMEM (2 * STG)   // 48 KB

__device__ float        g_partials[NPART];
__device__ unsigned int g_count;

__constant__ int c_tileI[NPT] = {0,0,0,0,1,1,1,2,2,3};
__constant__ int c_tileJ[NPT] = {0,1,2,3,1,2,3,2,3,3};

// ---------- helpers ----------
__device__ __forceinline__ uint32_t smem_u32(const void* p) {
    uint32_t a;
    asm("{ .reg .u64 t; cvta.to.shared.u64 t, %1; cvt.u32.u64 %0, t; }" : "=r"(a) : "l"(p));
    return a;
}
// swizzled byte offset: row stride 64B (32 bf16), conflict-free for STS.64 + ldmatrix
__device__ __forceinline__ uint32_t swz(uint32_t row, uint32_t k) {
    return row * 64u + ((((k >> 3) ^ (row >> 1)) & 3u) << 4) + (k & 7u) * 2u;
}
__device__ __forceinline__ uint32_t pack2(float hi, float lo) {
    uint32_t r;
    asm("cvt.rn.bf16x2.f32 %0, %1, %2;" : "=r"(r) : "f"(hi), "f"(lo));
    return r;
}
__device__ __forceinline__ void sts64(uint32_t addr, uint32_t a, uint32_t b) {
    asm volatile("st.shared.v2.b32 [%0], {%1, %2};" :: "r"(addr), "r"(a), "r"(b) : "memory");
}
__device__ __forceinline__ void ldm_x4(uint32_t* r, uint32_t addr) {
    asm volatile("ldmatrix.sync.aligned.m8n8.x4.shared.b16 {%0,%1,%2,%3}, [%4];"
                 : "=r"(r[0]), "=r"(r[1]), "=r"(r[2]), "=r"(r[3]) : "r"(addr));
}
__device__ __forceinline__ void mma_bf16(float* d, const uint32_t* a, const uint32_t* b) {
    asm volatile("mma.sync.aligned.m16n8k16.row.col.f32.bf16.bf16.f32 "
                 "{%0,%1,%2,%3}, {%4,%5,%6,%7}, {%8,%9}, {%0,%1,%2,%3};"
                 : "+f"(d[0]), "+f"(d[1]), "+f"(d[2]), "+f"(d[3])
                 : "r"(a[0]), "r"(a[1]), "r"(a[2]), "r"(a[3]), "r"(b[0]), "r"(b[1]));
}

// one k16 step for one gram: A rows [arow0, arow0+32), B rows [brow0, brow0+32)
__device__ __forceinline__ void mma_ks(uint32_t pA, int arow0, uint32_t pB, int brow0,
                                       int k0, int lane, float acc[2][4][4]) {
    const int a_row = lane & 15;
    const int a_k   = (lane >> 4) << 3;
    const int b_row = (((lane >> 4) & 1) << 3) + (lane & 7);
    const int b_k   = ((lane >> 3) & 1) << 3;
    uint32_t af[2][4], bf[4][2];
    #pragma unroll
    for (int mt = 0; mt < 2; mt++)
        ldm_x4(af[mt], pA + swz(arow0 + mt * 16 + a_row, k0 + a_k));
    #pragma unroll
    for (int tp = 0; tp < 2; tp++) {
        uint32_t t4[4];
        ldm_x4(t4, pB + swz(brow0 + tp * 16 + b_row, k0 + b_k));
        bf[2 * tp][0] = t4[0]; bf[2 * tp][1] = t4[1];
        bf[2 * tp + 1][0] = t4[2]; bf[2 * tp + 1][1] = t4[3];
    }
    #pragma unroll
    for (int mt = 0; mt < 2; mt++)
        #pragma unroll
        for (int nt = 0; nt < 4; nt++)
            mma_bf16(acc[mt][nt], af[mt], bf[nt]);
}

// ---------- main kernel ----------
__global__ __launch_bounds__(256, 2)
void gram_kernel(const float* __restrict__ F, const float* __restrict__ Dm,
                 float* __restrict__ out) {
    extern __shared__ __align__(128) unsigned char smem[];
    __shared__ float red[256];
    __shared__ unsigned int s_islast;

    const int tid  = threadIdx.x;
    const int lane = tid & 31;
    const int wid  = tid >> 5;
    const int b    = blockIdx.y;
    const int pt   = blockIdx.x >> 1;
    const int h    = blockIdx.x & 1;
    const int I = c_tileI[pt];
    const int J = c_tileJ[pt];
    const int diag = (I == J);
    const float w = diag ? 1.0f : 2.0f;

    // global row bases
    const float* BFg = F  + ((size_t)b * C_ + J * 128) * HW_;             // 128 rows
    const float* BDg = Dm + ((size_t)b * C_ + J * 128) * HW_;
    const float* AFg = F  + ((size_t)b * C_ + I * 128 + h * 64) * HW_;    // 64 rows
    const float* ADg = Dm + ((size_t)b * C_ + I * 128 + h * 64) * HW_;

    const uint32_t sbase = smem_u32(smem);
    const int aoff = diag ? h * 64 : 0;   // A-row offset inside its panel

    // warp tiling: 2x4 warps, warp tile 32(m) x 32(n)
    const int wm = wid >> 2;
    const int wn = wid & 3;
    const int arow0 = aoff + wm * 32;
    const int brow0 = wn * 32;

    // loader coords: B panel slot idx = tid + i*256 (i<4): row=idx>>3, seg=idx&7
    const int lrowB = tid >> 3;      // +32 per i
    const int lseg  = tid & 7;

    float accE[2][4][4], accD[2][4][4];
    #pragma unroll
    for (int mt = 0; mt < 2; mt++)
        #pragma unroll
        for (int nt = 0; nt < 4; nt++)
            #pragma unroll
            for (int r = 0; r < 4; r++) { accE[mt][nt][r] = 0.f; accD[mt][nt][r] = 0.f; }

    // ---- prologue: chunk 0 into stage 0 ----
    {
        #pragma unroll
        for (int i = 0; i < 4; i++) {
            int row = lrowB + i * 32;
            float4 v = *(const float4*)(BFg + (size_t)row * HW_ + lseg * 4);
            sts64(sbase + OBF + swz(row, lseg * 4), pack2(v.y, v.x), pack2(v.w, v.z));
            float4 u = *(const float4*)(BDg + (size_t)row * HW_ + lseg * 4);
            sts64(sbase + OBD + swz(row, lseg * 4), pack2(u.y, u.x), pack2(u.w, u.z));
        }
        if (!diag) {
            #pragma unroll
            for (int i = 0; i < 2; i++) {
                int row = lrowB + i * 32;
                float4 v = *(const float4*)(AFg + (size_t)row * HW_ + lseg * 4);
                sts64(sbase + OAF + swz(row, lseg * 4), pack2(v.y, v.x), pack2(v.w, v.z));
                float4 u = *(const float4*)(ADg + (size_t)row * HW_ + lseg * 4);
                sts64(sbase + OAD + swz(row, lseg * 4), pack2(u.y, u.x), pack2(u.w, u.z));
            }
        }
    }
    __syncthreads();

    // ---- main loop ----
    for (int c = 0; c < NCH; c++) {
        const int s = c & 1;
        const uint32_t stb  = sbase + s * STG;
        const uint32_t nstb = sbase + (s ^ 1) * STG;
        const uint32_t pBF = stb + OBF;
        const uint32_t pBD = stb + OBD;
        const uint32_t pAF = diag ? (stb + OBF) : (stb + OAF);
        const uint32_t pAD = diag ? (stb + OBD) : (stb + OAD);
        const bool more = (c + 1 < NCH);
        const int k1 = (c + 1) * KC;

        float4 st[4];
        // load BF(next) ; enc ks0+ks1
        if (more) {
            #pragma unroll
            for (int i = 0; i < 4; i++)
                st[i] = *(const float4*)(BFg + (size_t)(lrowB + i * 32) * HW_ + k1 + lseg * 4);
        }
        mma_ks(pAF, arow0, pBF, brow0, 0,  lane, accE);
        mma_ks(pAF, arow0, pBF, brow0, 16, lane, accE);
        // store BF ; load BD(next) ; dec ks0
        if (more) {
            #pragma unroll
            for (int i = 0; i < 4; i++) {
                float4 v = st[i];
                sts64(nstb + OBF + swz(lrowB + i * 32, lseg * 4), pack2(v.y, v.x), pack2(v.w, v.z));
            }
            #pragma unroll
            for (int i = 0; i < 4; i++)
                st[i] = *(const float4*)(BDg + (size_t)(lrowB + i * 32) * HW_ + k1 + lseg * 4);
        }
        mma_ks(pAD, arow0, pBD, brow0, 0, lane, accD);
        // store BD ; load AF+AD(next) ; dec ks1
        if (more) {
            #pragma unroll
            for (int i = 0; i < 4; i++) {
                float4 v = st[i];
                sts64(nstb + OBD + swz(lrowB + i * 32, lseg * 4), pack2(v.y, v.x), pack2(v.w, v.z));
            }
            if (!diag) {
                #pragma unroll
                for (int i = 0; i < 2; i++) {
                    st[i]     = *(const float4*)(AFg + (size_t)(lrowB + i * 32) * HW_ + k1 + lseg * 4);
                    st[i + 2] = *(const float4*)(ADg + (size_t)(lrowB + i * 32) * HW_ + k1 + lseg * 4);
                }
            }
        }
        mma_ks(pAD, arow0, pBD, brow0, 16, lane, accD);
        // store AF+AD
        if (more && !diag) {
            #pragma unroll
            for (int i = 0; i < 2; i++) {
                float4 v = st[i], u = st[i + 2];
                sts64(nstb + OAF + swz(lrowB + i * 32, lseg * 4), pack2(v.y, v.x), pack2(v.w, v.z));
                sts64(nstb + OAD + swz(lrowB + i * 32, lseg * 4), pack2(u.y, u.x), pack2(u.w, u.z));
            }
        }
        __syncthreads();
    }

    // ---- epilogue ----
    float local = 0.f;
    #pragma unroll
    for (int mt = 0; mt < 2; mt++)
        #pragma unroll
        for (int nt = 0; nt < 4; nt++)
            #pragma unroll
            for (int r = 0; r < 4; r++) {
                float dv = accD[mt][nt][r] - accE[mt][nt][r];
                local = fmaf(dv, dv, local);
            }

    red[tid] = local;
    __syncthreads();
    #pragma unroll
    for (int stp = 128; stp > 0; stp >>= 1) {
        if (tid < stp) red[tid] += red[tid + stp];
        __syncthreads();
    }

    if (tid == 0) {
        g_partials[b * NHT + blockIdx.x] = w * red[0];
        __threadfence();
        unsigned int prev = atomicAdd(&g_count, 1u);
        s_islast = (prev == NPART - 1) ? 1u : 0u;
    }
    __syncthreads();
    if (s_islast) {
        __threadfence();
        float v = 0.f;
        for (int i = tid; i < NPART; i += 256) v += g_partials[i];
        red[tid] = v;
        __syncthreads();
        #pragma unroll
        for (int stp = 128; stp > 0; stp >>= 1) {
            if (tid < stp) red[tid] += red[tid + stp];
            __syncthreads();
        }
        if (tid == 0) {
            out[0] = red[0] * (1.0f / 1099511627776.0f);  // / 2^40
            g_count = 0;  // reset for next graph replay
        }
    }
}

extern "C" void kernel_launch(void* const* d_in, const int* in_sizes, int n_in,
                              void* d_out, int out_size) {
    const float* F = (const float*)d_in[0];   // feat
    const float* D = (const float*)d_in[1];   // feat_decod
    float* out = (float*)d_out;

    cudaFuncSetAttribute(gram_kernel, cudaFuncAttributeMaxDynamicSharedMemorySize, DYN_SMEM);
    dim3 grid(NHT, B_);
    gram_kernel<<<grid, 256, DYN_SMEM>>>(F, D, out);
}